// round 9
// baseline (speedup 1.0000x reference)
#include <cuda_runtime.h>
#include <cuda_fp16.h>
#include <cuda_bf16.h>
#include <cstdint>
#include <cstddef>

#define B_  128
#define S_  512
#define I_  128
#define H_  128
#define M_  8
#define KD_ 16
#define R_  16
#define O_  128
#define MH_ 1024

#define OUT_OUTPUTS 0ull
#define OUT_HID     8388608ull
#define OUT_AIN     75497472ull
#define OUT_ACM     142606336ull
#define OUT_ATTN    209715200ull

// ---------------- scratch ----------------
__device__ float g_P[(size_t)S_ * B_ * MH_];
__device__ float g_Wcomb[M_ * I_ * H_];
__device__ float g_biasP[MH_];
__device__ __align__(16) __nv_bfloat16 g_BinT_hi[M_ * 16384];
__device__ __align__(16) __nv_bfloat16 g_BinT_lo[M_ * 16384];
__device__ __align__(16) __nv_bfloat16 g_BpT_hi[M_ * 16384];
__device__ __align__(16) __nv_bfloat16 g_BpT_lo[M_ * 16384];
__device__ __align__(16) __nv_bfloat16 g_Wo_hi[O_ * MH_];
__device__ __align__(16) __nv_bfloat16 g_Wo_lo[O_ * MH_];

// ---------------- helpers ----------------
__device__ __forceinline__ uint32_t smem_u32(const void* p) {
    uint32_t a;
    asm("{ .reg .u64 t; cvta.to.shared.u64 t, %1; cvt.u32.u64 %0, t; }" : "=r"(a) : "l"(p));
    return a;
}
__device__ __forceinline__ uint32_t swb(int n, int k) {
    uint32_t byte = ((uint32_t)((n >> 3) + (k >> 6) * 16)) * 1024u
                  + (uint32_t)(n & 7) * 128u + (uint32_t)(k & 63) * 2u;
    return byte ^ ((byte >> 3) & 0x70u);
}
__device__ __forceinline__ void split1(float v, uint16_t& h, uint16_t& l) {
    __nv_bfloat16 bh = __float2bfloat16(v);
    float r = v - __bfloat162float(bh);
    h = __bfloat16_as_ushort(bh);
    l = __bfloat16_as_ushort(__float2bfloat16(r));
}
__device__ __forceinline__ void ldsm4(uint32_t* r, uint32_t addr) {
    asm volatile("ldmatrix.sync.aligned.m8n8.x4.shared.b16 {%0,%1,%2,%3}, [%4];"
                 : "=r"(r[0]), "=r"(r[1]), "=r"(r[2]), "=r"(r[3]) : "r"(addr));
}
__device__ __forceinline__ void mma16816(float* c, const uint32_t* a, const uint32_t* b) {
    asm volatile("mma.sync.aligned.m16n8k16.row.col.f32.bf16.bf16.f32 "
                 "{%0,%1,%2,%3}, {%4,%5,%6,%7}, {%8,%9}, {%0,%1,%2,%3};"
                 : "+f"(c[0]), "+f"(c[1]), "+f"(c[2]), "+f"(c[3])
                 : "r"(a[0]), "r"(a[1]), "r"(a[2]), "r"(a[3]), "r"(b[0]), "r"(b[1]));
}

#define A_HI 0
#define A_LO 32768
#define B_HI 65536
#define B_LO 98304
#define GEMM_SMEM 131072

// ---------------------------------------------------------------------------
// prep 0: Wcomb[m,i,o] = sum_h W_in[m,i,h] * Wp[m,o,h]
// ---------------------------------------------------------------------------
__global__ void __launch_bounds__(256) prep_wcomb(const float* __restrict__ W_in,
                                                  const float* __restrict__ Wp) {
    extern __shared__ float s0[];
    float* Wins = s0;
    float* Wps  = s0 + 16384;   // stride 129
    int m = blockIdx.x, tid = threadIdx.x;
    const float* wi = W_in + m * 16384;
    const float* wp = Wp   + m * 16384;
    for (int i = tid; i < 16384; i += 256) {
        Wins[i] = wi[i];
        Wps[(i >> 7) * 129 + (i & 127)] = wp[i];
    }
    __syncthreads();
    for (int idx = tid; idx < 16384; idx += 256) {
        int j = idx >> 7, o = idx & 127;
        const float* a = Wins + j * 128;
        const float* b = Wps + o * 129;
        float acc = 0.f;
#pragma unroll 16
        for (int i = 0; i < 128; ++i) acc += a[i] * b[i];
        g_Wcomb[m * 16384 + idx] = acc;
    }
}

// ---------------------------------------------------------------------------
// prep 1: transpose + bf16-split weights, combine biases
// ---------------------------------------------------------------------------
__global__ void __launch_bounds__(256) prep_split(const float* __restrict__ W_in,
                                                  const float* __restrict__ Wo,
                                                  const float* __restrict__ bp,
                                                  const float* __restrict__ cbias) {
    int b = blockIdx.x, tid = threadIdx.x;
    if (b < 8) {
        int m = b;
        for (int idx = tid; idx < 16384; idx += 256) {
            int h = idx >> 7, i = idx & 127;
            uint16_t hi, lo;
            split1(W_in[m * 16384 + i * 128 + h], hi, lo);
            g_BinT_hi[m * 16384 + idx] = __ushort_as_bfloat16(hi);
            g_BinT_lo[m * 16384 + idx] = __ushort_as_bfloat16(lo);
        }
    } else if (b < 16) {
        int m = b - 8;
        for (int idx = tid; idx < 16384; idx += 256) {
            int o = idx >> 7, i = idx & 127;
            uint16_t hi, lo;
            split1(g_Wcomb[m * 16384 + i * 128 + o], hi, lo);
            g_BpT_hi[m * 16384 + idx] = __ushort_as_bfloat16(hi);
            g_BpT_lo[m * 16384 + idx] = __ushort_as_bfloat16(lo);
        }
    } else if (b < 32) {
        int s = b - 16;
        for (int idx = tid; idx < 8192; idx += 256) {
            int g = s * 8192 + idx;
            uint16_t hi, lo;
            split1(Wo[g], hi, lo);
            g_Wo_hi[g] = __ushort_as_bfloat16(hi);
            g_Wo_lo[g] = __ushort_as_bfloat16(lo);
        }
    } else {
        for (int idx = tid; idx < MH_; idx += 256) g_biasP[idx] = bp[idx] + cbias[idx];
    }
}

// ---------------------------------------------------------------------------
// GEMM A (mma.sync bf16-split)
// ---------------------------------------------------------------------------
__global__ void __launch_bounds__(256)
gemm_in_mma(const float* __restrict__ x, float* __restrict__ out) {
    extern __shared__ char smc[];
    uint32_t sb = smem_u32(smc);
    int tid = threadIdx.x, w = tid >> 5, lane = tid & 31, t = blockIdx.x;

    {
        int rb = tid >> 1, half = tid & 1;
        const float4* xr = (const float4*)(x + ((size_t)rb * S_ + t) * I_ + half * 64);
#pragma unroll
        for (int q = 0; q < 16; ++q) {
            float4 v = xr[q];
            int k0 = half * 64 + q * 4;
            uint16_t h0, h1, h2, h3, l0, l1, l2, l3;
            split1(v.x, h0, l0); split1(v.y, h1, l1);
            split1(v.z, h2, l2); split1(v.w, h3, l3);
            uint2 hv = make_uint2((uint32_t)h0 | ((uint32_t)h1 << 16),
                                  (uint32_t)h2 | ((uint32_t)h3 << 16));
            uint2 lv = make_uint2((uint32_t)l0 | ((uint32_t)l1 << 16),
                                  (uint32_t)l2 | ((uint32_t)l3 << 16));
            uint32_t off = swb(rb, k0);
            *(uint2*)(smc + A_HI + off) = hv;
            *(uint2*)(smc + A_LO + off) = lv;
        }
    }

    int lq = lane >> 3, ll = lane & 7;
    int a_row = w * 16 + ll + (lq & 1) * 8;
    int a_kadd = (lq >> 1) * 8;
    int b_rc = (lq >> 1) * 8 + ll;
    int b_kadd = (lq & 1) * 8;
    int c_row = w * 16 + (lane >> 2);
    int c_col = (lane & 3) * 2;

    for (int blk = 0; blk < 16; ++blk) {
        int m = blk & 7;
        bool isP = blk >= 8;
        const __nv_bfloat16* gh = (isP ? g_BpT_hi : g_BinT_hi) + m * 16384;
        const __nv_bfloat16* gl = (isP ? g_BpT_lo : g_BinT_lo) + m * 16384;
#pragma unroll
        for (int q = 0; q < 8; ++q) {
            int u = tid + q * 256;
            int n = u >> 4, k0 = (u & 15) * 8;
            uint4 vh = ((const uint4*)gh)[u];
            uint4 vl = ((const uint4*)gl)[u];
            uint32_t off = swb(n, k0);
            *(uint4*)(smc + B_HI + off) = vh;
            *(uint4*)(smc + B_LO + off) = vl;
        }
        __syncthreads();

        float c[16][4];
#pragma unroll
        for (int i = 0; i < 16; ++i)
#pragma unroll
            for (int j = 0; j < 4; ++j) c[i][j] = 0.f;

        for (int ks = 0; ks < 8; ++ks) {
            int k0 = ks * 16;
            uint32_t ah[4], al[4];
            uint32_t aoff = swb(a_row, k0 + a_kadd);
            ldsm4(ah, sb + A_HI + aoff);
            ldsm4(al, sb + A_LO + aoff);
#pragma unroll
            for (int np = 0; np < 8; ++np) {
                uint32_t bh[4], bl[4];
                uint32_t boff = swb(np * 16 + b_rc, k0 + b_kadd);
                ldsm4(bh, sb + B_HI + boff);
                ldsm4(bl, sb + B_LO + boff);
                mma16816(c[2 * np],     ah, bh);
                mma16816(c[2 * np],     ah, bl);
                mma16816(c[2 * np],     al, bh);
                mma16816(c[2 * np + 1], ah, bh + 2);
                mma16816(c[2 * np + 1], ah, bl + 2);
                mma16816(c[2 * np + 1], al, bh + 2);
            }
        }

        if (!isP) {
            float* d0 = out + OUT_AIN + ((size_t)t * B_ + c_row) * MH_ + m * H_;
            float* d1 = out + OUT_AIN + ((size_t)t * B_ + c_row + 8) * MH_ + m * H_;
#pragma unroll
            for (int nt = 0; nt < 16; ++nt) {
                int col = nt * 8 + c_col;
                *(float2*)(d0 + col) = make_float2(c[nt][0], c[nt][1]);
                *(float2*)(d1 + col) = make_float2(c[nt][2], c[nt][3]);
            }
        } else {
            float* d0 = g_P + ((size_t)t * B_ + c_row) * MH_ + m * H_;
            float* d1 = g_P + ((size_t)t * B_ + c_row + 8) * MH_ + m * H_;
#pragma unroll
            for (int nt = 0; nt < 16; ++nt) {
                int col = nt * 8 + c_col;
                float2 bi = *(const float2*)(g_biasP + m * H_ + col);
                *(float2*)(d0 + col) = make_float2(c[nt][0] + bi.x, c[nt][1] + bi.y);
                *(float2*)(d1 + col) = make_float2(c[nt][2] + bi.x, c[nt][3] + bi.y);
            }
        }
        __syncthreads();
    }
}

// ---------------------------------------------------------------------------
// GEMM C (mma.sync bf16-split)
// ---------------------------------------------------------------------------
__global__ void __launch_bounds__(256)
gemm_out_mma(const float* __restrict__ bo, float* __restrict__ out) {
    extern __shared__ char smc[];
    uint32_t sb = smem_u32(smc);
    int tid = threadIdx.x, w = tid >> 5, lane = tid & 31, t = blockIdx.x;
    const float* hid = out + OUT_HID + (size_t)t * B_ * MH_;

    int lq = lane >> 3, ll = lane & 7;
    int a_row = w * 16 + ll + (lq & 1) * 8;
    int a_kadd = (lq >> 1) * 8;
    int b_rc = (lq >> 1) * 8 + ll;
    int b_kadd = (lq & 1) * 8;
    int c_row = w * 16 + (lane >> 2);
    int c_col = (lane & 3) * 2;

    float c[16][4];
#pragma unroll
    for (int i = 0; i < 16; ++i)
#pragma unroll
        for (int j = 0; j < 4; ++j) c[i][j] = 0.f;

    for (int kc = 0; kc < 8; ++kc) {
        {
            int rb = tid >> 1, half = tid & 1;
            const float4* ar = (const float4*)(hid + (size_t)rb * MH_ + kc * 128 + half * 64);
#pragma unroll
            for (int q = 0; q < 16; ++q) {
                float4 v = ar[q];
                int k0 = half * 64 + q * 4;
                uint16_t h0, h1, h2, h3, l0, l1, l2, l3;
                split1(v.x, h0, l0); split1(v.y, h1, l1);
                split1(v.z, h2, l2); split1(v.w, h3, l3);
                uint2 hv = make_uint2((uint32_t)h0 | ((uint32_t)h1 << 16),
                                      (uint32_t)h2 | ((uint32_t)h3 << 16));
                uint2 lv = make_uint2((uint32_t)l0 | ((uint32_t)l1 << 16),
                                      (uint32_t)l2 | ((uint32_t)l3 << 16));
                uint32_t off = swb(rb, k0);
                *(uint2*)(smc + A_HI + off) = hv;
                *(uint2*)(smc + A_LO + off) = lv;
            }
        }
#pragma unroll
        for (int q = 0; q < 8; ++q) {
            int u = tid + q * 256;
            int n = u >> 4, k0 = (u & 15) * 8;
            uint4 vh = *(const uint4*)(g_Wo_hi + (size_t)n * MH_ + kc * 128 + k0);
            uint4 vl = *(const uint4*)(g_Wo_lo + (size_t)n * MH_ + kc * 128 + k0);
            uint32_t off = swb(n, k0);
            *(uint4*)(smc + B_HI + off) = vh;
            *(uint4*)(smc + B_LO + off) = vl;
        }
        __syncthreads();

        for (int ks = 0; ks < 8; ++ks) {
            int k0 = ks * 16;
            uint32_t ah[4], al[4];
            uint32_t aoff = swb(a_row, k0 + a_kadd);
            ldsm4(ah, sb + A_HI + aoff);
            ldsm4(al, sb + A_LO + aoff);
#pragma unroll
            for (int np = 0; np < 8; ++np) {
                uint32_t bh[4], bl[4];
                uint32_t boff = swb(np * 16 + b_rc, k0 + b_kadd);
                ldsm4(bh, sb + B_HI + boff);
                ldsm4(bl, sb + B_LO + boff);
                mma16816(c[2 * np],     ah, bh);
                mma16816(c[2 * np],     ah, bl);
                mma16816(c[2 * np],     al, bh);
                mma16816(c[2 * np + 1], ah, bh + 2);
                mma16816(c[2 * np + 1], ah, bl + 2);
                mma16816(c[2 * np + 1], al, bh + 2);
            }
        }
        __syncthreads();
    }

    float* d0 = out + OUT_OUTPUTS + ((size_t)c_row * S_ + t) * O_;
    float* d1 = out + OUT_OUTPUTS + ((size_t)(c_row + 8) * S_ + t) * O_;
#pragma unroll
    for (int nt = 0; nt < 16; ++nt) {
        int col = nt * 8 + c_col;
        float2 bi = *(const float2*)(bo + col);
        *(float2*)(d0 + col) = make_float2(c[nt][0] + bi.x, c[nt][1] + bi.y);
        *(float2*)(d1 + col) = make_float2(c[nt][2] + bi.x, c[nt][3] + bi.y);
    }
}

// ---------------------------------------------------------------------------
// Kernel B: sequential recurrence — mechanism-parallel warps, 2 batches/CTA.
// 512 threads: group g = tid>>8 handles batch blockIdx.x*2+g with warps 0-7
// of that group (warp = mechanism). Groups sync independently via named
// barriers; shared read-only weights, private state blocks.
// ---------------------------------------------------------------------------
#define UT_F   (128 * 132)                                  // 16896 floats
#define WT_H   (256 * 136)                                  // 34816 halves
#define ST_F   (3 * 1024 + 3 * 128)                         // 3456 floats/state
#define SEQ_SMEM ((UT_F + 16384) * 4 + WT_H * 2 + 2 * ST_F * 4)   // 230400 B

__global__ void __launch_bounds__(512) rim_seq_kernel(const float* __restrict__ U,
                                                      const float* __restrict__ V,
                                                      const float* __restrict__ WQ,
                                                      const float* __restrict__ WK,
                                                      const float* __restrict__ WV,
                                                      float* __restrict__ out) {
    extern __shared__ float smf[];
    float* Ut  = smf;                          // [(m*16+r)][h] stride 132
    float* Vs  = Ut + UT_F;                    // [m][r][h] linear
    __half* Wt = (__half*)(Vs + 16384);        // [(m*32+j)][h] stride 136
    float* stateBase = (float*)(Wt + WT_H);

    int tid = threadIdx.x, g = tid >> 8, ltid = tid & 255;
    int w = ltid >> 5, lane = ltid & 31;       // w = mechanism
    int b = blockIdx.x * 2 + g;
    int h4 = lane * 4;

    float* st  = stateBase + g * ST_F;
    float* his = st;
    float* vcs = st + 1024;
    float* Ssm = st + 2048;
    float* tmp = st + 3072;                    // [m*16+r]
    float* Kc  = tmp + 128;                    // [m*16+k]
    float* Qc  = Kc + 128;

    // ---- init (cooperative over all 512 threads)
    for (int i = tid; i < 16384; i += 512) {
        int m = i >> 11, h = (i >> 4) & 127, k = i & 15;   // U/WK/WQ layout [m][h][k]
        Ut[(m * 16 + k) * 132 + h] = U[i];
        Wt[(m * 32 + k) * 136 + h] = __float2half(WK[i]);
        Wt[(m * 32 + 16 + k) * 136 + h] = __float2half(WQ[i]);
        Vs[i] = V[i];                                      // V is [m][r][h]
    }
    // per-lane diag(W_V) in registers
    float4 wv4;
    wv4.x = WV[w * 16384 + (h4 + 0) * 128 + (h4 + 0)];
    wv4.y = WV[w * 16384 + (h4 + 1) * 128 + (h4 + 1)];
    wv4.z = WV[w * 16384 + (h4 + 2) * 128 + (h4 + 2)];
    wv4.w = WV[w * 16384 + (h4 + 3) * 128 + (h4 + 3)];
    *(float4*)(Ssm + w * 128 + h4) = make_float4(0.f, 0.f, 0.f, 0.f);
    __syncthreads();

    // group-scoped barrier (256 threads, id 1+g)
#define GBAR() asm volatile("bar.sync %0, %1;" :: "r"(g + 1), "r"(256) : "memory")

    // roles
    int r_a = lane >> 1, half_a = lane & 1;
    const float* Ua = Ut + (w * 16 + r_a) * 132 + half_a * 64;
    const float* Sa = Ssm + w * 128 + half_a * 64;
    const float* Vb = Vs + w * 2048 + h4;
    const float* Tb = tmp + w * 16;
    const __half* Wr = Wt + (w * 32 + lane) * 136;
    const float* Hm = his + w * 128;
    int md = lane >> 2, n0 = (lane & 3) * 2;

    float4 p4 = *(const float4*)(g_P + (size_t)b * MH_ + w * 128 + h4);

    for (int t = 0; t < S_; ++t) {
        // ---- a: tmp[w,r] = sum_h Ssm[w,h] * U[w,h,r]
        {
            float c0 = 0.f, c1 = 0.f, c2 = 0.f, c3 = 0.f;
#pragma unroll
            for (int j = 0; j < 16; ++j) {
                float4 u = *(const float4*)(Ua + j * 4);
                float4 s = *(const float4*)(Sa + j * 4);
                c0 += u.x * s.x; c1 += u.y * s.y;
                c2 += u.z * s.z; c3 += u.w * s.w;
            }
            float acc = (c0 + c1) + (c2 + c3);
            acc += __shfl_xor_sync(0xffffffffu, acc, 1);
            if (half_a == 0) tmp[w * 16 + r_a] = acc;
        }
        GBAR();   // BARRIER-1

        // ---- b: hin = tanh(P + tmp.V); write his/vcs
        float4 hin;
        {
            float4 z = p4;
#pragma unroll
            for (int r = 0; r < 16; ++r) {
                float tr = Tb[r];
                float4 v = *(const float4*)(Vb + r * 128);
                z.x += tr * v.x; z.y += tr * v.y;
                z.z += tr * v.z; z.w += tr * v.w;
            }
            hin.x = tanhf(z.x); hin.y = tanhf(z.y);
            hin.z = tanhf(z.z); hin.w = tanhf(z.w);
            *(float4*)(his + w * 128 + h4) = hin;
            *(float4*)(vcs + w * 128 + h4) = make_float4(hin.x * wv4.x, hin.y * wv4.y,
                                                         hin.z * wv4.z, hin.w * wv4.w);
        }
        __syncwarp();

        // ---- c: Kc/Qc[w,k] = sum_h his[w,h] * W[w,h,k]
        {
            float c0 = 0.f, c1 = 0.f, c2 = 0.f, c3 = 0.f;
#pragma unroll
            for (int j = 0; j < 16; ++j) {
                uint4 w8 = *(const uint4*)(Wr + j * 8);
                float4 x0 = *(const float4*)(Hm + j * 8);
                float4 x1 = *(const float4*)(Hm + j * 8 + 4);
                float2 f;
                f = __half22float2(*(__half2*)&w8.x); c0 += x0.x * f.x; c1 += x0.y * f.y;
                f = __half22float2(*(__half2*)&w8.y); c2 += x0.z * f.x; c3 += x0.w * f.y;
                f = __half22float2(*(__half2*)&w8.z); c0 += x1.x * f.x; c1 += x1.y * f.y;
                f = __half22float2(*(__half2*)&w8.w); c2 += x1.z * f.x; c3 += x1.w * f.y;
            }
            float acc = (c0 + c1) + (c2 + c3);
            float* Xc = (lane < 16) ? Kc : Qc;
            Xc[w * 16 + (lane & 15)] = acc;
        }
        GBAR();   // BARRIER-2

        // prefetch next P during d/e shadow
        float4 pn;
        {
            int tn = (t + 1) & (S_ - 1);
            pn = *(const float4*)(g_P + ((size_t)tn * B_ + b) * MH_ + w * 128 + h4);
        }

        // ---- d: redundant per-warp softmax
        float a0, a1;
        {
            const float* qrow = Qc + md * 16;
            const float* k0r = Kc + n0 * 16;
            const float* k1r = k0r + 16;
            float lg0 = 0.f, lg1 = 0.f;
#pragma unroll
            for (int k4 = 0; k4 < 16; k4 += 4) {
                float4 q = *(const float4*)(qrow + k4);
                float4 ka = *(const float4*)(k0r + k4);
                float4 kb = *(const float4*)(k1r + k4);
                lg0 += q.x * ka.x + q.y * ka.y + q.z * ka.z + q.w * ka.w;
                lg1 += q.x * kb.x + q.y * kb.y + q.z * kb.z + q.w * kb.w;
            }
            lg0 *= 0.25f; lg1 *= 0.25f;
            float mx = fmaxf(lg0, lg1);
            mx = fmaxf(mx, __shfl_xor_sync(0xffffffffu, mx, 1));
            mx = fmaxf(mx, __shfl_xor_sync(0xffffffffu, mx, 2));
            float e0 = expf(lg0 - mx), e1 = expf(lg1 - mx);
            float sm2 = e0 + e1;
            sm2 += __shfl_xor_sync(0xffffffffu, sm2, 1);
            sm2 += __shfl_xor_sync(0xffffffffu, sm2, 2);
            float inv = 1.0f / sm2;
            a0 = e0 * inv; a1 = e1 * inv;
            if (w == 0)
                *(float2*)(out + OUT_ATTN + ((size_t)t * B_ + b) * 64 + md * 8 + n0)
                    = make_float2(a0, a1);
        }

        // ---- e: A_comm[w,h] = sum_m attn[m,w]*vcs[m,h]; H_new = H_in + A_comm
        {
            float sel = (w & 1) ? a1 : a0;
            int srcq = w >> 1;
            float4 ac = make_float4(0.f, 0.f, 0.f, 0.f);
#pragma unroll
            for (int mm = 0; mm < 8; ++mm) {
                float av = __shfl_sync(0xffffffffu, sel, mm * 4 + srcq);
                float4 v = *(const float4*)(vcs + mm * 128 + h4);
                ac.x += av * v.x; ac.y += av * v.y;
                ac.z += av * v.z; ac.w += av * v.w;
            }
            float4 hnew = make_float4(hin.x + ac.x, hin.y + ac.y,
                                      hin.z + ac.z, hin.w + ac.w);
            size_t gbase = ((size_t)t * B_ + b) * MH_ + w * 128 + h4;
            *(float4*)(out + OUT_ACM + gbase) = ac;
            *(float4*)(out + OUT_HID + gbase) = hnew;
            *(float4*)(Ssm + w * 128 + h4) = hnew;
        }
        p4 = pn;
    }
#undef GBAR
}

extern "C" void kernel_launch(void* const* d_in, const int* in_sizes, int n_in,
                              void* d_out, int out_size) {
    const float* x     = (const float*)d_in[0];
    const float* Wp    = (const float*)d_in[1];
    const float* bp    = (const float*)d_in[2];
    const float* U     = (const float*)d_in[3];
    const float* V     = (const float*)d_in[4];
    const float* cbias = (const float*)d_in[5];
    const float* W_in  = (const float*)d_in[6];
    const float* W_Q   = (const float*)d_in[7];
    const float* W_K   = (const float*)d_in[8];
    const float* W_V   = (const float*)d_in[9];
    const float* Wo    = (const float*)d_in[10];
    const float* bo    = (const float*)d_in[11];
    float* out = (float*)d_out;

    static bool attr_done = false;
    if (!attr_done) {
        cudaFuncSetAttribute(prep_wcomb,     cudaFuncAttributeMaxDynamicSharedMemorySize, 132608);
        cudaFuncSetAttribute(gemm_in_mma,    cudaFuncAttributeMaxDynamicSharedMemorySize, GEMM_SMEM);
        cudaFuncSetAttribute(gemm_out_mma,   cudaFuncAttributeMaxDynamicSharedMemorySize, GEMM_SMEM);
        cudaFuncSetAttribute(rim_seq_kernel, cudaFuncAttributeMaxDynamicSharedMemorySize, SEQ_SMEM);
        attr_done = true;
    }

    prep_wcomb<<<M_, 256, 132608>>>(W_in, Wp);
    prep_split<<<33, 256>>>(W_in, Wo, bp, cbias);
    gemm_in_mma<<<S_, 256, GEMM_SMEM>>>(x, out);
    rim_seq_kernel<<<B_ / 2, 512, SEQ_SMEM>>>(U, V, W_Q, W_K, W_V, out);
    gemm_out_mma<<<S_, 256, GEMM_SMEM>>>(bo, out);
}

// round 11
// speedup vs baseline: 1.7910x; 1.7910x over previous
#include <cuda_runtime.h>
#include <cuda_fp16.h>
#include <cuda_bf16.h>
#include <cstdint>
#include <cstddef>

#define B_  128
#define S_  512
#define I_  128
#define H_  128
#define M_  8
#define KD_ 16
#define R_  16
#define O_  128
#define MH_ 1024

#define OUT_OUTPUTS 0ull
#define OUT_HID     8388608ull
#define OUT_AIN     75497472ull
#define OUT_ACM     142606336ull
#define OUT_ATTN    209715200ull

// ---------------- scratch ----------------
__device__ float g_P[(size_t)S_ * B_ * MH_];
__device__ float g_Wcomb[M_ * I_ * H_];
__device__ float g_biasP[MH_];
__device__ __align__(16) __nv_bfloat16 g_BinT_hi[M_ * 16384];
__device__ __align__(16) __nv_bfloat16 g_BinT_lo[M_ * 16384];
__device__ __align__(16) __nv_bfloat16 g_BpT_hi[M_ * 16384];
__device__ __align__(16) __nv_bfloat16 g_BpT_lo[M_ * 16384];
__device__ __align__(16) __nv_bfloat16 g_Wo_hi[O_ * MH_];
__device__ __align__(16) __nv_bfloat16 g_Wo_lo[O_ * MH_];

// ---------------- helpers ----------------
__device__ __forceinline__ uint32_t smem_u32(const void* p) {
    uint32_t a;
    asm("{ .reg .u64 t; cvta.to.shared.u64 t, %1; cvt.u32.u64 %0, t; }" : "=r"(a) : "l"(p));
    return a;
}
__device__ __forceinline__ uint32_t swb(int n, int k) {
    uint32_t byte = ((uint32_t)((n >> 3) + (k >> 6) * 16)) * 1024u
                  + (uint32_t)(n & 7) * 128u + (uint32_t)(k & 63) * 2u;
    return byte ^ ((byte >> 3) & 0x70u);
}
__device__ __forceinline__ void split1(float v, uint16_t& h, uint16_t& l) {
    __nv_bfloat16 bh = __float2bfloat16(v);
    float r = v - __bfloat162float(bh);
    h = __bfloat16_as_ushort(bh);
    l = __bfloat16_as_ushort(__float2bfloat16(r));
}
__device__ __forceinline__ void ldsm4(uint32_t* r, uint32_t addr) {
    asm volatile("ldmatrix.sync.aligned.m8n8.x4.shared.b16 {%0,%1,%2,%3}, [%4];"
                 : "=r"(r[0]), "=r"(r[1]), "=r"(r[2]), "=r"(r[3]) : "r"(addr));
}
__device__ __forceinline__ void mma16816(float* c, const uint32_t* a, const uint32_t* b) {
    asm volatile("mma.sync.aligned.m16n8k16.row.col.f32.bf16.bf16.f32 "
                 "{%0,%1,%2,%3}, {%4,%5,%6,%7}, {%8,%9}, {%0,%1,%2,%3};"
                 : "+f"(c[0]), "+f"(c[1]), "+f"(c[2]), "+f"(c[3])
                 : "r"(a[0]), "r"(a[1]), "r"(a[2]), "r"(a[3]), "r"(b[0]), "r"(b[1]));
}
__device__ __forceinline__ float tanhf_fast(float x) {
    float ax = fabsf(x);
    float e = __expf(-2.0f * ax);
    float r = __fdividef(1.0f - e, 1.0f + e);
    return copysignf(r, x);
}

#define A_HI 0
#define A_LO 32768
#define B_HI 65536
#define B_LO 98304
#define GEMM_SMEM 131072

// ---------------------------------------------------------------------------
// prep 0: Wcomb[m,i,o] = sum_h W_in[m,i,h] * Wp[m,o,h]
// ---------------------------------------------------------------------------
__global__ void __launch_bounds__(256) prep_wcomb(const float* __restrict__ W_in,
                                                  const float* __restrict__ Wp) {
    extern __shared__ float s0[];
    float* Wins = s0;
    float* Wps  = s0 + 16384;   // stride 129
    int m = blockIdx.x, tid = threadIdx.x;
    const float* wi = W_in + m * 16384;
    const float* wp = Wp   + m * 16384;
    for (int i = tid; i < 16384; i += 256) {
        Wins[i] = wi[i];
        Wps[(i >> 7) * 129 + (i & 127)] = wp[i];
    }
    __syncthreads();
    for (int idx = tid; idx < 16384; idx += 256) {
        int j = idx >> 7, o = idx & 127;
        const float* a = Wins + j * 128;
        const float* b = Wps + o * 129;
        float acc = 0.f;
#pragma unroll 16
        for (int i = 0; i < 128; ++i) acc += a[i] * b[i];
        g_Wcomb[m * 16384 + idx] = acc;
    }
}

// ---------------------------------------------------------------------------
// prep 1: transpose + bf16-split weights, combine biases
// ---------------------------------------------------------------------------
__global__ void __launch_bounds__(256) prep_split(const float* __restrict__ W_in,
                                                  const float* __restrict__ Wo,
                                                  const float* __restrict__ bp,
                                                  const float* __restrict__ cbias) {
    int b = blockIdx.x, tid = threadIdx.x;
    if (b < 8) {
        int m = b;
        for (int idx = tid; idx < 16384; idx += 256) {
            int h = idx >> 7, i = idx & 127;
            uint16_t hi, lo;
            split1(W_in[m * 16384 + i * 128 + h], hi, lo);
            g_BinT_hi[m * 16384 + idx] = __ushort_as_bfloat16(hi);
            g_BinT_lo[m * 16384 + idx] = __ushort_as_bfloat16(lo);
        }
    } else if (b < 16) {
        int m = b - 8;
        for (int idx = tid; idx < 16384; idx += 256) {
            int o = idx >> 7, i = idx & 127;
            uint16_t hi, lo;
            split1(g_Wcomb[m * 16384 + i * 128 + o], hi, lo);
            g_BpT_hi[m * 16384 + idx] = __ushort_as_bfloat16(hi);
            g_BpT_lo[m * 16384 + idx] = __ushort_as_bfloat16(lo);
        }
    } else if (b < 32) {
        int s = b - 16;
        for (int idx = tid; idx < 8192; idx += 256) {
            int g = s * 8192 + idx;
            uint16_t hi, lo;
            split1(Wo[g], hi, lo);
            g_Wo_hi[g] = __ushort_as_bfloat16(hi);
            g_Wo_lo[g] = __ushort_as_bfloat16(lo);
        }
    } else {
        for (int idx = tid; idx < MH_; idx += 256) g_biasP[idx] = bp[idx] + cbias[idx];
    }
}

// ---------------------------------------------------------------------------
// GEMM A (mma.sync bf16-split)
// ---------------------------------------------------------------------------
__global__ void __launch_bounds__(256)
gemm_in_mma(const float* __restrict__ x, float* __restrict__ out) {
    extern __shared__ char smc[];
    uint32_t sb = smem_u32(smc);
    int tid = threadIdx.x, w = tid >> 5, lane = tid & 31, t = blockIdx.x;

    {
        int rb = tid >> 1, half = tid & 1;
        const float4* xr = (const float4*)(x + ((size_t)rb * S_ + t) * I_ + half * 64);
#pragma unroll
        for (int q = 0; q < 16; ++q) {
            float4 v = xr[q];
            int k0 = half * 64 + q * 4;
            uint16_t h0, h1, h2, h3, l0, l1, l2, l3;
            split1(v.x, h0, l0); split1(v.y, h1, l1);
            split1(v.z, h2, l2); split1(v.w, h3, l3);
            uint2 hv = make_uint2((uint32_t)h0 | ((uint32_t)h1 << 16),
                                  (uint32_t)h2 | ((uint32_t)h3 << 16));
            uint2 lv = make_uint2((uint32_t)l0 | ((uint32_t)l1 << 16),
                                  (uint32_t)l2 | ((uint32_t)l3 << 16));
            uint32_t off = swb(rb, k0);
            *(uint2*)(smc + A_HI + off) = hv;
            *(uint2*)(smc + A_LO + off) = lv;
        }
    }

    int lq = lane >> 3, ll = lane & 7;
    int a_row = w * 16 + ll + (lq & 1) * 8;
    int a_kadd = (lq >> 1) * 8;
    int b_rc = (lq >> 1) * 8 + ll;
    int b_kadd = (lq & 1) * 8;
    int c_row = w * 16 + (lane >> 2);
    int c_col = (lane & 3) * 2;

    for (int blk = 0; blk < 16; ++blk) {
        int m = blk & 7;
        bool isP = blk >= 8;
        const __nv_bfloat16* gh = (isP ? g_BpT_hi : g_BinT_hi) + m * 16384;
        const __nv_bfloat16* gl = (isP ? g_BpT_lo : g_BinT_lo) + m * 16384;
#pragma unroll
        for (int q = 0; q < 8; ++q) {
            int u = tid + q * 256;
            int n = u >> 4, k0 = (u & 15) * 8;
            uint4 vh = ((const uint4*)gh)[u];
            uint4 vl = ((const uint4*)gl)[u];
            uint32_t off = swb(n, k0);
            *(uint4*)(smc + B_HI + off) = vh;
            *(uint4*)(smc + B_LO + off) = vl;
        }
        __syncthreads();

        float c[16][4];
#pragma unroll
        for (int i = 0; i < 16; ++i)
#pragma unroll
            for (int j = 0; j < 4; ++j) c[i][j] = 0.f;

        for (int ks = 0; ks < 8; ++ks) {
            int k0 = ks * 16;
            uint32_t ah[4], al[4];
            uint32_t aoff = swb(a_row, k0 + a_kadd);
            ldsm4(ah, sb + A_HI + aoff);
            ldsm4(al, sb + A_LO + aoff);
#pragma unroll
            for (int np = 0; np < 8; ++np) {
                uint32_t bh[4], bl[4];
                uint32_t boff = swb(np * 16 + b_rc, k0 + b_kadd);
                ldsm4(bh, sb + B_HI + boff);
                ldsm4(bl, sb + B_LO + boff);
                mma16816(c[2 * np],     ah, bh);
                mma16816(c[2 * np],     ah, bl);
                mma16816(c[2 * np],     al, bh);
                mma16816(c[2 * np + 1], ah, bh + 2);
                mma16816(c[2 * np + 1], ah, bl + 2);
                mma16816(c[2 * np + 1], al, bh + 2);
            }
        }

        if (!isP) {
            float* d0 = out + OUT_AIN + ((size_t)t * B_ + c_row) * MH_ + m * H_;
            float* d1 = out + OUT_AIN + ((size_t)t * B_ + c_row + 8) * MH_ + m * H_;
#pragma unroll
            for (int nt = 0; nt < 16; ++nt) {
                int col = nt * 8 + c_col;
                *(float2*)(d0 + col) = make_float2(c[nt][0], c[nt][1]);
                *(float2*)(d1 + col) = make_float2(c[nt][2], c[nt][3]);
            }
        } else {
            float* d0 = g_P + ((size_t)t * B_ + c_row) * MH_ + m * H_;
            float* d1 = g_P + ((size_t)t * B_ + c_row + 8) * MH_ + m * H_;
#pragma unroll
            for (int nt = 0; nt < 16; ++nt) {
                int col = nt * 8 + c_col;
                float2 bi = *(const float2*)(g_biasP + m * H_ + col);
                *(float2*)(d0 + col) = make_float2(c[nt][0] + bi.x, c[nt][1] + bi.y);
                *(float2*)(d1 + col) = make_float2(c[nt][2] + bi.x, c[nt][3] + bi.y);
            }
        }
        __syncthreads();
    }
}

// ---------------------------------------------------------------------------
// GEMM C (mma.sync bf16-split)
// ---------------------------------------------------------------------------
__global__ void __launch_bounds__(256)
gemm_out_mma(const float* __restrict__ bo, float* __restrict__ out) {
    extern __shared__ char smc[];
    uint32_t sb = smem_u32(smc);
    int tid = threadIdx.x, w = tid >> 5, lane = tid & 31, t = blockIdx.x;
    const float* hid = out + OUT_HID + (size_t)t * B_ * MH_;

    int lq = lane >> 3, ll = lane & 7;
    int a_row = w * 16 + ll + (lq & 1) * 8;
    int a_kadd = (lq >> 1) * 8;
    int b_rc = (lq >> 1) * 8 + ll;
    int b_kadd = (lq & 1) * 8;
    int c_row = w * 16 + (lane >> 2);
    int c_col = (lane & 3) * 2;

    float c[16][4];
#pragma unroll
    for (int i = 0; i < 16; ++i)
#pragma unroll
        for (int j = 0; j < 4; ++j) c[i][j] = 0.f;

    for (int kc = 0; kc < 8; ++kc) {
        {
            int rb = tid >> 1, half = tid & 1;
            const float4* ar = (const float4*)(hid + (size_t)rb * MH_ + kc * 128 + half * 64);
#pragma unroll
            for (int q = 0; q < 16; ++q) {
                float4 v = ar[q];
                int k0 = half * 64 + q * 4;
                uint16_t h0, h1, h2, h3, l0, l1, l2, l3;
                split1(v.x, h0, l0); split1(v.y, h1, l1);
                split1(v.z, h2, l2); split1(v.w, h3, l3);
                uint2 hv = make_uint2((uint32_t)h0 | ((uint32_t)h1 << 16),
                                      (uint32_t)h2 | ((uint32_t)h3 << 16));
                uint2 lv = make_uint2((uint32_t)l0 | ((uint32_t)l1 << 16),
                                      (uint32_t)l2 | ((uint32_t)l3 << 16));
                uint32_t off = swb(rb, k0);
                *(uint2*)(smc + A_HI + off) = hv;
                *(uint2*)(smc + A_LO + off) = lv;
            }
        }
#pragma unroll
        for (int q = 0; q < 8; ++q) {
            int u = tid + q * 256;
            int n = u >> 4, k0 = (u & 15) * 8;
            uint4 vh = *(const uint4*)(g_Wo_hi + (size_t)n * MH_ + kc * 128 + k0);
            uint4 vl = *(const uint4*)(g_Wo_lo + (size_t)n * MH_ + kc * 128 + k0);
            uint32_t off = swb(n, k0);
            *(uint4*)(smc + B_HI + off) = vh;
            *(uint4*)(smc + B_LO + off) = vl;
        }
        __syncthreads();

        for (int ks = 0; ks < 8; ++ks) {
            int k0 = ks * 16;
            uint32_t ah[4], al[4];
            uint32_t aoff = swb(a_row, k0 + a_kadd);
            ldsm4(ah, sb + A_HI + aoff);
            ldsm4(al, sb + A_LO + aoff);
#pragma unroll
            for (int np = 0; np < 8; ++np) {
                uint32_t bh[4], bl[4];
                uint32_t boff = swb(np * 16 + b_rc, k0 + b_kadd);
                ldsm4(bh, sb + B_HI + boff);
                ldsm4(bl, sb + B_LO + boff);
                mma16816(c[2 * np],     ah, bh);
                mma16816(c[2 * np],     ah, bl);
                mma16816(c[2 * np],     al, bh);
                mma16816(c[2 * np + 1], ah, bh + 2);
                mma16816(c[2 * np + 1], ah, bl + 2);
                mma16816(c[2 * np + 1], al, bh + 2);
            }
        }
        __syncthreads();
    }

    float* d0 = out + OUT_OUTPUTS + ((size_t)c_row * S_ + t) * O_;
    float* d1 = out + OUT_OUTPUTS + ((size_t)(c_row + 8) * S_ + t) * O_;
#pragma unroll
    for (int nt = 0; nt < 16; ++nt) {
        int col = nt * 8 + c_col;
        float2 bi = *(const float2*)(bo + col);
        *(float2*)(d0 + col) = make_float2(c[nt][0] + bi.x, c[nt][1] + bi.y);
        *(float2*)(d1 + col) = make_float2(c[nt][2] + bi.x, c[nt][3] + bi.y);
    }
}

// ---------------------------------------------------------------------------
// Kernel B: sequential recurrence — mechanism-parallel warps,
// U and V fully register-resident (fp32), state in registers,
// W_QK fp16 in smem (validated), double-buffered vcs/Kc/Qc,
// ONE __syncthreads per step. 256 threads, grid = 128.
// smem: half Wt[256*136] | float his[1024] | vcs[2][1024] | KQ[2][256]
// ---------------------------------------------------------------------------
#define WT_HALFS (256 * 136)     // 34816
#define SEQ_SMEM (WT_HALFS * 2 + (1024 + 2048 + 512) * 4)    // 83968 B

__global__ void __launch_bounds__(256) rim_seq_kernel(const float* __restrict__ U,
                                                      const float* __restrict__ V,
                                                      const float* __restrict__ WQ,
                                                      const float* __restrict__ WK,
                                                      const float* __restrict__ WV,
                                                      float* __restrict__ out) {
    extern __shared__ char smc[];
    __half* Wt = (__half*)smc;                       // [(m*32+j)][h] stride 136
    float* his = (float*)(Wt + WT_HALFS);            // [1024]
    float* vcsB = his + 1024;                        // [2][1024]
    float* KQB = vcsB + 2048;                        // [2][256]: Kc then Qc

    int tid = threadIdx.x, b = blockIdx.x;
    int w = tid >> 5, lane = tid & 31;               // w = mechanism
    int h4 = lane * 4;

    // ---- init Wt (fp16 W_K/W_Q)
    for (int i = tid; i < 16384; i += 256) {
        int m = i >> 11, h = (i >> 4) & 127, k = i & 15;   // layout [m][h][k]
        Wt[(m * 32 + k) * 136 + h] = __float2half(WK[i]);
        Wt[(m * 32 + 16 + k) * 136 + h] = __float2half(WQ[i]);
    }

    // ---- U into registers: Ur[j][r] = U[w][h4+j][r]   (64 regs)
    float Ur[4][16];
#pragma unroll
    for (int j = 0; j < 4; ++j) {
        const float4* ur = (const float4*)(U + w * 2048 + (h4 + j) * 16);
#pragma unroll
        for (int q = 0; q < 4; ++q) {
            float4 v = ur[q];
            Ur[j][q * 4 + 0] = v.x; Ur[j][q * 4 + 1] = v.y;
            Ur[j][q * 4 + 2] = v.z; Ur[j][q * 4 + 3] = v.w;
        }
    }
    // ---- V into registers: Vr[r] = V[w][r][h4..h4+3]   (64 regs)
    float4 Vr[16];
#pragma unroll
    for (int r = 0; r < 16; ++r)
        Vr[r] = *(const float4*)(V + w * 2048 + r * 128 + h4);

    float4 wv4;
    wv4.x = WV[w * 16384 + (h4 + 0) * 128 + (h4 + 0)];
    wv4.y = WV[w * 16384 + (h4 + 1) * 128 + (h4 + 1)];
    wv4.z = WV[w * 16384 + (h4 + 2) * 128 + (h4 + 2)];
    wv4.w = WV[w * 16384 + (h4 + 3) * 128 + (h4 + 3)];

    float4 s = make_float4(0.f, 0.f, 0.f, 0.f);      // state S[h4..h4+3]
    __syncthreads();

    // roles
    const __half* Wr = Wt + (w * 32 + lane) * 136;
    const float* Hm = his + w * 128;
    int md = lane >> 2, n0 = (lane & 3) * 2;

    float4 p4 = *(const float4*)(g_P + (size_t)b * MH_ + w * 128 + h4);
    int par = 0;

    for (int t = 0; t < S_; ++t) {
        float* vcs = vcsB + par * 1024;
        float* Kc = KQB + par * 256;
        float* Qc = Kc + 128;

        // ---- a: part[r] = sum over own 4 h, then 5-stage butterfly
        //         -> every lane holds full tmp[0..15]
        float part[16];
#pragma unroll
        for (int r = 0; r < 16; ++r)
            part[r] = s.x * Ur[0][r] + s.y * Ur[1][r] + s.z * Ur[2][r] + s.w * Ur[3][r];
#pragma unroll
        for (int st = 16; st >= 1; st >>= 1)
#pragma unroll
            for (int r = 0; r < 16; ++r)
                part[r] += __shfl_xor_sync(0xffffffffu, part[r], st);

        // ---- b: hin = tanh(P + tmp.V)  (pure register math)
        float4 hin;
        {
            float4 z = p4;
#pragma unroll
            for (int r = 0; r < 16; ++r) {
                z.x += part[r] * Vr[r].x; z.y += part[r] * Vr[r].y;
                z.z += part[r] * Vr[r].z; z.w += part[r] * Vr[r].w;
            }
            hin.x = tanhf_fast(z.x); hin.y = tanhf_fast(z.y);
            hin.z = tanhf_fast(z.z); hin.w = tanhf_fast(z.w);
            *(float4*)(his + w * 128 + h4) = hin;
            *(float4*)(vcs + w * 128 + h4) = make_float4(hin.x * wv4.x, hin.y * wv4.y,
                                                         hin.z * wv4.z, hin.w * wv4.w);
        }
        __syncwarp();

        // ---- c: Kc/Qc[w,k] = sum_h his[w,h] * W[w,h,k]
        {
            float c0 = 0.f, c1 = 0.f, c2 = 0.f, c3 = 0.f;
#pragma unroll
            for (int j = 0; j < 16; ++j) {
                uint4 w8 = *(const uint4*)(Wr + j * 8);
                float4 x0 = *(const float4*)(Hm + j * 8);
                float4 x1 = *(const float4*)(Hm + j * 8 + 4);
                float2 f;
                f = __half22float2(*(__half2*)&w8.x); c0 += x0.x * f.x; c1 += x0.y * f.y;
                f = __half22float2(*(__half2*)&w8.y); c2 += x0.z * f.x; c3 += x0.w * f.y;
                f = __half22float2(*(__half2*)&w8.z); c0 += x1.x * f.x; c1 += x1.y * f.y;
                f = __half22float2(*(__half2*)&w8.w); c2 += x1.z * f.x; c3 += x1.w * f.y;
            }
            float acc = (c0 + c1) + (c2 + c3);
            float* Xc = (lane < 16) ? Kc : Qc;
            Xc[w * 16 + (lane & 15)] = acc;
        }
        __syncthreads();   // the ONLY block barrier: publish Kc/Qc/vcs

        // prefetch next P during d/e shadow
        float4 pn;
        {
            int tn = (t + 1) & (S_ - 1);
            pn = *(const float4*)(g_P + ((size_t)tn * B_ + b) * MH_ + w * 128 + h4);
        }

        // ---- d: redundant per-warp softmax
        float a0, a1;
        {
            const float* qrow = Qc + md * 16;
            const float* k0r = Kc + n0 * 16;
            const float* k1r = k0r + 16;
            float lg0 = 0.f, lg1 = 0.f;
#pragma unroll
            for (int k4 = 0; k4 < 16; k4 += 4) {
                float4 q = *(const float4*)(qrow + k4);
                float4 ka = *(const float4*)(k0r + k4);
                float4 kb = *(const float4*)(k1r + k4);
                lg0 += q.x * ka.x + q.y * ka.y + q.z * ka.z + q.w * ka.w;
                lg1 += q.x * kb.x + q.y * kb.y + q.z * kb.z + q.w * kb.w;
            }
            lg0 *= 0.25f; lg1 *= 0.25f;
            float mx = fmaxf(lg0, lg1);
            mx = fmaxf(mx, __shfl_xor_sync(0xffffffffu, mx, 1));
            mx = fmaxf(mx, __shfl_xor_sync(0xffffffffu, mx, 2));
            float e0 = __expf(lg0 - mx), e1 = __expf(lg1 - mx);
            float sm2 = e0 + e1;
            sm2 += __shfl_xor_sync(0xffffffffu, sm2, 1);
            sm2 += __shfl_xor_sync(0xffffffffu, sm2, 2);
            float inv = __fdividef(1.0f, sm2);
            a0 = e0 * inv; a1 = e1 * inv;
            if (w == 0)
                *(float2*)(out + OUT_ATTN + ((size_t)t * B_ + b) * 64 + md * 8 + n0)
                    = make_float2(a0, a1);
        }

        // ---- e: A_comm[w,h] = sum_m attn[m,w]*vcs[m,h]; state update in regs
        {
            float sel = (w & 1) ? a1 : a0;
            int srcq = w >> 1;
            float4 ac = make_float4(0.f, 0.f, 0.f, 0.f);
#pragma unroll
            for (int mm = 0; mm < 8; ++mm) {
                float av = __shfl_sync(0xffffffffu, sel, mm * 4 + srcq);
                float4 v = *(const float4*)(vcs + mm * 128 + h4);
                ac.x += av * v.x; ac.y += av * v.y;
                ac.z += av * v.z; ac.w += av * v.w;
            }
            float4 hnew = make_float4(hin.x + ac.x, hin.y + ac.y,
                                      hin.z + ac.z, hin.w + ac.w);
            size_t gbase = ((size_t)t * B_ + b) * MH_ + w * 128 + h4;
            *(float4*)(out + OUT_ACM + gbase) = ac;
            *(float4*)(out + OUT_HID + gbase) = hnew;
            s = hnew;
        }
        p4 = pn;
        par ^= 1;
    }
}

extern "C" void kernel_launch(void* const* d_in, const int* in_sizes, int n_in,
                              void* d_out, int out_size) {
    const float* x     = (const float*)d_in[0];
    const float* Wp    = (const float*)d_in[1];
    const float* bp    = (const float*)d_in[2];
    const float* U     = (const float*)d_in[3];
    const float* V     = (const float*)d_in[4];
    const float* cbias = (const float*)d_in[5];
    const float* W_in  = (const float*)d_in[6];
    const float* W_Q   = (const float*)d_in[7];
    const float* W_K   = (const float*)d_in[8];
    const float* W_V   = (const float*)d_in[9];
    const float* Wo    = (const float*)d_in[10];
    const float* bo    = (const float*)d_in[11];
    float* out = (float*)d_out;

    static bool attr_done = false;
    if (!attr_done) {
        cudaFuncSetAttribute(prep_wcomb,     cudaFuncAttributeMaxDynamicSharedMemorySize, 132608);
        cudaFuncSetAttribute(gemm_in_mma,    cudaFuncAttributeMaxDynamicSharedMemorySize, GEMM_SMEM);
        cudaFuncSetAttribute(gemm_out_mma,   cudaFuncAttributeMaxDynamicSharedMemorySize, GEMM_SMEM);
        cudaFuncSetAttribute(rim_seq_kernel, cudaFuncAttributeMaxDynamicSharedMemorySize, SEQ_SMEM);
        attr_done = true;
    }

    prep_wcomb<<<M_, 256, 132608>>>(W_in, Wp);
    prep_split<<<33, 256>>>(W_in, Wo, bp, cbias);
    gemm_in_mma<<<S_, 256, GEMM_SMEM>>>(x, out);
    rim_seq_kernel<<<B_, 256, SEQ_SMEM>>>(U, V, W_Q, W_K, W_V, out);
    gemm_out_mma<<<S_, 256, GEMM_SMEM>>>(bo, out);
}

// round 13
// speedup vs baseline: 1.9230x; 1.0737x over previous
#include <cuda_runtime.h>
#include <cuda_fp16.h>
#include <cuda_bf16.h>
#include <cstdint>
#include <cstddef>

#define B_  128
#define S_  512
#define I_  128
#define H_  128
#define M_  8
#define KD_ 16
#define R_  16
#define O_  128
#define MH_ 1024

#define OUT_OUTPUTS 0ull
#define OUT_HID     8388608ull
#define OUT_AIN     75497472ull
#define OUT_ACM     142606336ull
#define OUT_ATTN    209715200ull

// ---------------- scratch ----------------
__device__ float g_P[(size_t)S_ * B_ * MH_];
__device__ float g_Wcomb[M_ * I_ * H_];
__device__ float g_biasP[MH_];
__device__ __align__(16) __nv_bfloat16 g_BinT_hi[M_ * 16384];
__device__ __align__(16) __nv_bfloat16 g_BinT_lo[M_ * 16384];
__device__ __align__(16) __nv_bfloat16 g_BpT_hi[M_ * 16384];
__device__ __align__(16) __nv_bfloat16 g_BpT_lo[M_ * 16384];
__device__ __align__(16) __nv_bfloat16 g_Wo_hi[O_ * MH_];
__device__ __align__(16) __nv_bfloat16 g_Wo_lo[O_ * MH_];

// ---------------- helpers ----------------
__device__ __forceinline__ uint32_t smem_u32(const void* p) {
    uint32_t a;
    asm("{ .reg .u64 t; cvta.to.shared.u64 t, %1; cvt.u32.u64 %0, t; }" : "=r"(a) : "l"(p));
    return a;
}
__device__ __forceinline__ uint32_t swb(int n, int k) {
    uint32_t byte = ((uint32_t)((n >> 3) + (k >> 6) * 16)) * 1024u
                  + (uint32_t)(n & 7) * 128u + (uint32_t)(k & 63) * 2u;
    return byte ^ ((byte >> 3) & 0x70u);
}
__device__ __forceinline__ void split1(float v, uint16_t& h, uint16_t& l) {
    __nv_bfloat16 bh = __float2bfloat16(v);
    float r = v - __bfloat162float(bh);
    h = __bfloat16_as_ushort(bh);
    l = __bfloat16_as_ushort(__float2bfloat16(r));
}
__device__ __forceinline__ void ldsm4(uint32_t* r, uint32_t addr) {
    asm volatile("ldmatrix.sync.aligned.m8n8.x4.shared.b16 {%0,%1,%2,%3}, [%4];"
                 : "=r"(r[0]), "=r"(r[1]), "=r"(r[2]), "=r"(r[3]) : "r"(addr));
}
__device__ __forceinline__ void mma16816(float* c, const uint32_t* a, const uint32_t* b) {
    asm volatile("mma.sync.aligned.m16n8k16.row.col.f32.bf16.bf16.f32 "
                 "{%0,%1,%2,%3}, {%4,%5,%6,%7}, {%8,%9}, {%0,%1,%2,%3};"
                 : "+f"(c[0]), "+f"(c[1]), "+f"(c[2]), "+f"(c[3])
                 : "r"(a[0]), "r"(a[1]), "r"(a[2]), "r"(a[3]), "r"(b[0]), "r"(b[1]));
}
__device__ __forceinline__ float tanhf_fast(float x) {
    float ax = fabsf(x);
    float e = __expf(-2.0f * ax);
    float r = __fdividef(1.0f - e, 1.0f + e);
    return copysignf(r, x);
}

#define A_HI 0
#define A_LO 32768
#define B_HI 65536
#define B_LO 98304
#define GEMM_SMEM 131072

// ---------------------------------------------------------------------------
// prep 0: Wcomb[m,i,o] = sum_h W_in[m,i,h] * Wp[m,o,h]
// ---------------------------------------------------------------------------
__global__ void __launch_bounds__(256) prep_wcomb(const float* __restrict__ W_in,
                                                  const float* __restrict__ Wp) {
    extern __shared__ float s0[];
    float* Wins = s0;
    float* Wps  = s0 + 16384;   // stride 129
    int m = blockIdx.x, tid = threadIdx.x;
    const float* wi = W_in + m * 16384;
    const float* wp = Wp   + m * 16384;
    for (int i = tid; i < 16384; i += 256) {
        Wins[i] = wi[i];
        Wps[(i >> 7) * 129 + (i & 127)] = wp[i];
    }
    __syncthreads();
    for (int idx = tid; idx < 16384; idx += 256) {
        int j = idx >> 7, o = idx & 127;
        const float* a = Wins + j * 128;
        const float* b = Wps + o * 129;
        float acc = 0.f;
#pragma unroll 16
        for (int i = 0; i < 128; ++i) acc += a[i] * b[i];
        g_Wcomb[m * 16384 + idx] = acc;
    }
}

// ---------------------------------------------------------------------------
// prep 1: transpose + bf16-split weights, combine biases
// ---------------------------------------------------------------------------
__global__ void __launch_bounds__(256) prep_split(const float* __restrict__ W_in,
                                                  const float* __restrict__ Wo,
                                                  const float* __restrict__ bp,
                                                  const float* __restrict__ cbias) {
    int b = blockIdx.x, tid = threadIdx.x;
    if (b < 8) {
        int m = b;
        for (int idx = tid; idx < 16384; idx += 256) {
            int h = idx >> 7, i = idx & 127;
            uint16_t hi, lo;
            split1(W_in[m * 16384 + i * 128 + h], hi, lo);
            g_BinT_hi[m * 16384 + idx] = __ushort_as_bfloat16(hi);
            g_BinT_lo[m * 16384 + idx] = __ushort_as_bfloat16(lo);
        }
    } else if (b < 16) {
        int m = b - 8;
        for (int idx = tid; idx < 16384; idx += 256) {
            int o = idx >> 7, i = idx & 127;
            uint16_t hi, lo;
            split1(g_Wcomb[m * 16384 + i * 128 + o], hi, lo);
            g_BpT_hi[m * 16384 + idx] = __ushort_as_bfloat16(hi);
            g_BpT_lo[m * 16384 + idx] = __ushort_as_bfloat16(lo);
        }
    } else if (b < 32) {
        int s = b - 16;
        for (int idx = tid; idx < 8192; idx += 256) {
            int g = s * 8192 + idx;
            uint16_t hi, lo;
            split1(Wo[g], hi, lo);
            g_Wo_hi[g] = __ushort_as_bfloat16(hi);
            g_Wo_lo[g] = __ushort_as_bfloat16(lo);
        }
    } else {
        for (int idx = tid; idx < MH_; idx += 256) g_biasP[idx] = bp[idx] + cbias[idx];
    }
}

// ---------------------------------------------------------------------------
// GEMM A (mma.sync bf16-split)
// ---------------------------------------------------------------------------
__global__ void __launch_bounds__(256)
gemm_in_mma(const float* __restrict__ x, float* __restrict__ out) {
    extern __shared__ char smc[];
    uint32_t sb = smem_u32(smc);
    int tid = threadIdx.x, w = tid >> 5, lane = tid & 31, t = blockIdx.x;

    {
        int rb = tid >> 1, half = tid & 1;
        const float4* xr = (const float4*)(x + ((size_t)rb * S_ + t) * I_ + half * 64);
#pragma unroll
        for (int q = 0; q < 16; ++q) {
            float4 v = xr[q];
            int k0 = half * 64 + q * 4;
            uint16_t h0, h1, h2, h3, l0, l1, l2, l3;
            split1(v.x, h0, l0); split1(v.y, h1, l1);
            split1(v.z, h2, l2); split1(v.w, h3, l3);
            uint2 hv = make_uint2((uint32_t)h0 | ((uint32_t)h1 << 16),
                                  (uint32_t)h2 | ((uint32_t)h3 << 16));
            uint2 lv = make_uint2((uint32_t)l0 | ((uint32_t)l1 << 16),
                                  (uint32_t)l2 | ((uint32_t)l3 << 16));
            uint32_t off = swb(rb, k0);
            *(uint2*)(smc + A_HI + off) = hv;
            *(uint2*)(smc + A_LO + off) = lv;
        }
    }

    int lq = lane >> 3, ll = lane & 7;
    int a_row = w * 16 + ll + (lq & 1) * 8;
    int a_kadd = (lq >> 1) * 8;
    int b_rc = (lq >> 1) * 8 + ll;
    int b_kadd = (lq & 1) * 8;
    int c_row = w * 16 + (lane >> 2);
    int c_col = (lane & 3) * 2;

    for (int blk = 0; blk < 16; ++blk) {
        int m = blk & 7;
        bool isP = blk >= 8;
        const __nv_bfloat16* gh = (isP ? g_BpT_hi : g_BinT_hi) + m * 16384;
        const __nv_bfloat16* gl = (isP ? g_BpT_lo : g_BinT_lo) + m * 16384;
#pragma unroll
        for (int q = 0; q < 8; ++q) {
            int u = tid + q * 256;
            int n = u >> 4, k0 = (u & 15) * 8;
            uint4 vh = ((const uint4*)gh)[u];
            uint4 vl = ((const uint4*)gl)[u];
            uint32_t off = swb(n, k0);
            *(uint4*)(smc + B_HI + off) = vh;
            *(uint4*)(smc + B_LO + off) = vl;
        }
        __syncthreads();

        float c[16][4];
#pragma unroll
        for (int i = 0; i < 16; ++i)
#pragma unroll
            for (int j = 0; j < 4; ++j) c[i][j] = 0.f;

        for (int ks = 0; ks < 8; ++ks) {
            int k0 = ks * 16;
            uint32_t ah[4], al[4];
            uint32_t aoff = swb(a_row, k0 + a_kadd);
            ldsm4(ah, sb + A_HI + aoff);
            ldsm4(al, sb + A_LO + aoff);
#pragma unroll
            for (int np = 0; np < 8; ++np) {
                uint32_t bh[4], bl[4];
                uint32_t boff = swb(np * 16 + b_rc, k0 + b_kadd);
                ldsm4(bh, sb + B_HI + boff);
                ldsm4(bl, sb + B_LO + boff);
                mma16816(c[2 * np],     ah, bh);
                mma16816(c[2 * np],     ah, bl);
                mma16816(c[2 * np],     al, bh);
                mma16816(c[2 * np + 1], ah, bh + 2);
                mma16816(c[2 * np + 1], ah, bl + 2);
                mma16816(c[2 * np + 1], al, bh + 2);
            }
        }

        if (!isP) {
            float* d0 = out + OUT_AIN + ((size_t)t * B_ + c_row) * MH_ + m * H_;
            float* d1 = out + OUT_AIN + ((size_t)t * B_ + c_row + 8) * MH_ + m * H_;
#pragma unroll
            for (int nt = 0; nt < 16; ++nt) {
                int col = nt * 8 + c_col;
                *(float2*)(d0 + col) = make_float2(c[nt][0], c[nt][1]);
                *(float2*)(d1 + col) = make_float2(c[nt][2], c[nt][3]);
            }
        } else {
            float* d0 = g_P + ((size_t)t * B_ + c_row) * MH_ + m * H_;
            float* d1 = g_P + ((size_t)t * B_ + c_row + 8) * MH_ + m * H_;
#pragma unroll
            for (int nt = 0; nt < 16; ++nt) {
                int col = nt * 8 + c_col;
                float2 bi = *(const float2*)(g_biasP + m * H_ + col);
                *(float2*)(d0 + col) = make_float2(c[nt][0] + bi.x, c[nt][1] + bi.y);
                *(float2*)(d1 + col) = make_float2(c[nt][2] + bi.x, c[nt][3] + bi.y);
            }
        }
        __syncthreads();
    }
}

// ---------------------------------------------------------------------------
// GEMM C (mma.sync bf16-split)
// ---------------------------------------------------------------------------
__global__ void __launch_bounds__(256)
gemm_out_mma(const float* __restrict__ bo, float* __restrict__ out) {
    extern __shared__ char smc[];
    uint32_t sb = smem_u32(smc);
    int tid = threadIdx.x, w = tid >> 5, lane = tid & 31, t = blockIdx.x;
    const float* hid = out + OUT_HID + (size_t)t * B_ * MH_;

    int lq = lane >> 3, ll = lane & 7;
    int a_row = w * 16 + ll + (lq & 1) * 8;
    int a_kadd = (lq >> 1) * 8;
    int b_rc = (lq >> 1) * 8 + ll;
    int b_kadd = (lq & 1) * 8;
    int c_row = w * 16 + (lane >> 2);
    int c_col = (lane & 3) * 2;

    float c[16][4];
#pragma unroll
    for (int i = 0; i < 16; ++i)
#pragma unroll
        for (int j = 0; j < 4; ++j) c[i][j] = 0.f;

    for (int kc = 0; kc < 8; ++kc) {
        {
            int rb = tid >> 1, half = tid & 1;
            const float4* ar = (const float4*)(hid + (size_t)rb * MH_ + kc * 128 + half * 64);
#pragma unroll
            for (int q = 0; q < 16; ++q) {
                float4 v = ar[q];
                int k0 = half * 64 + q * 4;
                uint16_t h0, h1, h2, h3, l0, l1, l2, l3;
                split1(v.x, h0, l0); split1(v.y, h1, l1);
                split1(v.z, h2, l2); split1(v.w, h3, l3);
                uint2 hv = make_uint2((uint32_t)h0 | ((uint32_t)h1 << 16),
                                      (uint32_t)h2 | ((uint32_t)h3 << 16));
                uint2 lv = make_uint2((uint32_t)l0 | ((uint32_t)l1 << 16),
                                      (uint32_t)l2 | ((uint32_t)l3 << 16));
                uint32_t off = swb(rb, k0);
                *(uint2*)(smc + A_HI + off) = hv;
                *(uint2*)(smc + A_LO + off) = lv;
            }
        }
#pragma unroll
        for (int q = 0; q < 8; ++q) {
            int u = tid + q * 256;
            int n = u >> 4, k0 = (u & 15) * 8;
            uint4 vh = *(const uint4*)(g_Wo_hi + (size_t)n * MH_ + kc * 128 + k0);
            uint4 vl = *(const uint4*)(g_Wo_lo + (size_t)n * MH_ + kc * 128 + k0);
            uint32_t off = swb(n, k0);
            *(uint4*)(smc + B_HI + off) = vh;
            *(uint4*)(smc + B_LO + off) = vl;
        }
        __syncthreads();

        for (int ks = 0; ks < 8; ++ks) {
            int k0 = ks * 16;
            uint32_t ah[4], al[4];
            uint32_t aoff = swb(a_row, k0 + a_kadd);
            ldsm4(ah, sb + A_HI + aoff);
            ldsm4(al, sb + A_LO + aoff);
#pragma unroll
            for (int np = 0; np < 8; ++np) {
                uint32_t bh[4], bl[4];
                uint32_t boff = swb(np * 16 + b_rc, k0 + b_kadd);
                ldsm4(bh, sb + B_HI + boff);
                ldsm4(bl, sb + B_LO + boff);
                mma16816(c[2 * np],     ah, bh);
                mma16816(c[2 * np],     ah, bl);
                mma16816(c[2 * np],     al, bh);
                mma16816(c[2 * np + 1], ah, bh + 2);
                mma16816(c[2 * np + 1], ah, bl + 2);
                mma16816(c[2 * np + 1], al, bh + 2);
            }
        }
        __syncthreads();
    }

    float* d0 = out + OUT_OUTPUTS + ((size_t)c_row * S_ + t) * O_;
    float* d1 = out + OUT_OUTPUTS + ((size_t)(c_row + 8) * S_ + t) * O_;
#pragma unroll
    for (int nt = 0; nt < 16; ++nt) {
        int col = nt * 8 + c_col;
        float2 bi = *(const float2*)(bo + col);
        *(float2*)(d0 + col) = make_float2(c[nt][0] + bi.x, c[nt][1] + bi.y);
        *(float2*)(d1 + col) = make_float2(c[nt][2] + bi.x, c[nt][3] + bi.y);
    }
}

// ---------------------------------------------------------------------------
// Kernel B: sequential recurrence — mechanism-parallel warps, reg-resident
// U/V/state, reduce-scatter phase a, half2 phase c, ONE __syncthreads/step.
// 256 threads, grid = 128.
// smem: half Wt[256*136] | uint his_h[512] | float vcs[2][1024] | KQ[2][256]
// ---------------------------------------------------------------------------
#define WT_HALFS (256 * 136)     // 34816 halves = 69632 B
#define SEQ_SMEM (WT_HALFS * 2 + 512 * 4 + (2048 + 512) * 4)   // 81920 B

__global__ void __launch_bounds__(256) rim_seq_kernel(const float* __restrict__ U,
                                                      const float* __restrict__ V,
                                                      const float* __restrict__ WQ,
                                                      const float* __restrict__ WK,
                                                      const float* __restrict__ WV,
                                                      float* __restrict__ out) {
    extern __shared__ char smc[];
    __half* Wt = (__half*)smc;                       // [(m*32+j)][h] stride 136
    uint32_t* his_h = (uint32_t*)(Wt + WT_HALFS);    // [m][64] packed half2
    float* vcsB = (float*)(his_h + 512);             // [2][1024]
    float* KQB = vcsB + 2048;                        // [2][256]: Kc then Qc

    int tid = threadIdx.x, b = blockIdx.x;
    int w = tid >> 5, lane = tid & 31;               // w = mechanism
    int h4 = lane * 4;

    // ---- init Wt (fp16 W_K/W_Q)
    for (int i = tid; i < 16384; i += 256) {
        int m = i >> 11, h = (i >> 4) & 127, k = i & 15;   // layout [m][h][k]
        Wt[(m * 32 + k) * 136 + h] = __float2half(WK[i]);
        Wt[(m * 32 + 16 + k) * 136 + h] = __float2half(WQ[i]);
    }

    // ---- U into registers: Ur[j][r] = U[w][h4+j][r]
    float Ur[4][16];
#pragma unroll
    for (int j = 0; j < 4; ++j) {
        const float4* ur = (const float4*)(U + w * 2048 + (h4 + j) * 16);
#pragma unroll
        for (int q = 0; q < 4; ++q) {
            float4 v = ur[q];
            Ur[j][q * 4 + 0] = v.x; Ur[j][q * 4 + 1] = v.y;
            Ur[j][q * 4 + 2] = v.z; Ur[j][q * 4 + 3] = v.w;
        }
    }
    // ---- V into registers: Vr[r] = V[w][r][h4..h4+3]
    float4 Vr[16];
#pragma unroll
    for (int r = 0; r < 16; ++r)
        Vr[r] = *(const float4*)(V + w * 2048 + r * 128 + h4);

    float4 wv4;
    wv4.x = WV[w * 16384 + (h4 + 0) * 128 + (h4 + 0)];
    wv4.y = WV[w * 16384 + (h4 + 1) * 128 + (h4 + 1)];
    wv4.z = WV[w * 16384 + (h4 + 2) * 128 + (h4 + 2)];
    wv4.w = WV[w * 16384 + (h4 + 3) * 128 + (h4 + 3)];

    float4 s = make_float4(0.f, 0.f, 0.f, 0.f);      // state S[h4..h4+3]
    __syncthreads();

    // roles
    const __half* Wr = Wt + (w * 32 + lane) * 136;
    const uint4* Hm4 = (const uint4*)(his_h + w * 64);
    int md = lane >> 2, n0 = (lane & 3) * 2;

    float4 p4 = *(const float4*)(g_P + (size_t)b * MH_ + w * 128 + h4);
    int par = 0;

    for (int t = 0; t < S_; ++t) {
        float* vcs = vcsB + par * 1024;
        float* Kc = KQB + par * 256;
        float* Qc = Kc + 128;

        // ---- a: part[r] over own 4 h, then reduce-scatter (16 shfls total)
        float part[16];
#pragma unroll
        for (int r = 0; r < 16; ++r)
            part[r] = s.x * Ur[0][r] + s.y * Ur[1][r] + s.z * Ur[2][r] + s.w * Ur[3][r];
        {
            bool sel = (lane & 16) != 0;
#pragma unroll
            for (int j = 0; j < 8; ++j) {
                float keep = sel ? part[8 + j] : part[j];
                float send = sel ? part[j] : part[8 + j];
                part[j] = keep + __shfl_xor_sync(0xffffffffu, send, 16);
            }
        }
        {
            bool sel = (lane & 8) != 0;
#pragma unroll
            for (int j = 0; j < 4; ++j) {
                float keep = sel ? part[4 + j] : part[j];
                float send = sel ? part[j] : part[4 + j];
                part[j] = keep + __shfl_xor_sync(0xffffffffu, send, 8);
            }
        }
        {
            bool sel = (lane & 4) != 0;
#pragma unroll
            for (int j = 0; j < 2; ++j) {
                float keep = sel ? part[2 + j] : part[j];
                float send = sel ? part[j] : part[2 + j];
                part[j] = keep + __shfl_xor_sync(0xffffffffu, send, 4);
            }
        }
        {
            bool sel = (lane & 2) != 0;
            float keep = sel ? part[1] : part[0];
            float send = sel ? part[0] : part[1];
            part[0] = keep + __shfl_xor_sync(0xffffffffu, send, 2);
        }
        float tsum = part[0] + __shfl_xor_sync(0xffffffffu, part[0], 1);
        // lane l holds tmp[(l>>1)&15]

        // ---- b: hin = tanh(P + tmp.V); broadcast tmp via shfl
        float4 hin;
        {
            float4 z = p4;
#pragma unroll
            for (int r = 0; r < 16; ++r) {
                float tr = __shfl_sync(0xffffffffu, tsum, r << 1);
                z.x += tr * Vr[r].x; z.y += tr * Vr[r].y;
                z.z += tr * Vr[r].z; z.w += tr * Vr[r].w;
            }
            hin.x = tanhf_fast(z.x); hin.y = tanhf_fast(z.y);
            hin.z = tanhf_fast(z.z); hin.w = tanhf_fast(z.w);
            // pack H_in to half2 for phase c
            __half2 p01 = __floats2half2_rn(hin.x, hin.y);
            __half2 p23 = __floats2half2_rn(hin.z, hin.w);
            *(uint2*)(his_h + w * 64 + lane * 2) =
                make_uint2(*(uint32_t*)&p01, *(uint32_t*)&p23);
            *(float4*)(vcs + w * 128 + h4) = make_float4(hin.x * wv4.x, hin.y * wv4.y,
                                                         hin.z * wv4.z, hin.w * wv4.w);
        }
        __syncwarp();

        // ---- c: Kc/Qc[w,k] = sum_h H_half[w,h] * W_half[w,h,k]  (half2 math)
        {
            __half2 a0 = __float2half2_rn(0.f), a1 = a0, a2 = a0, a3 = a0;
#pragma unroll
            for (int j = 0; j < 16; ++j) {
                uint4 w8 = *(const uint4*)(Wr + j * 8);
                uint4 h8 = Hm4[j];
                a0 = __hfma2(*(__half2*)&w8.x, *(__half2*)&h8.x, a0);
                a1 = __hfma2(*(__half2*)&w8.y, *(__half2*)&h8.y, a1);
                a2 = __hfma2(*(__half2*)&w8.z, *(__half2*)&h8.z, a2);
                a3 = __hfma2(*(__half2*)&w8.w, *(__half2*)&h8.w, a3);
            }
            __half2 s01 = __hadd2(a0, a1);
            __half2 s23 = __hadd2(a2, a3);
            __half2 ss = __hadd2(s01, s23);
            float acc = __half2float(__low2half(ss)) + __half2float(__high2half(ss));
            float* Xc = (lane < 16) ? Kc : Qc;
            Xc[w * 16 + (lane & 15)] = acc;
        }
        __syncthreads();   // the ONLY block barrier: publish Kc/Qc/vcs

        // prefetch next P during d/e shadow
        float4 pn;
        {
            int tn = (t + 1) & (S_ - 1);
            pn = *(const float4*)(g_P + ((size_t)tn * B_ + b) * MH_ + w * 128 + h4);
        }

        // ---- d: redundant per-warp softmax
        float a0f, a1f;
        {
            const float* qrow = Qc + md * 16;
            const float* k0r = Kc + n0 * 16;
            const float* k1r = k0r + 16;
            float lg0 = 0.f, lg1 = 0.f;
#pragma unroll
            for (int k4 = 0; k4 < 16; k4 += 4) {
                float4 q = *(const float4*)(qrow + k4);
                float4 ka = *(const float4*)(k0r + k4);
                float4 kb = *(const float4*)(k1r + k4);
                lg0 += q.x * ka.x + q.y * ka.y + q.z * ka.z + q.w * ka.w;
                lg1 += q.x * kb.x + q.y * kb.y + q.z * kb.z + q.w * kb.w;
            }
            lg0 *= 0.25f; lg1 *= 0.25f;
            float mx = fmaxf(lg0, lg1);
            mx = fmaxf(mx, __shfl_xor_sync(0xffffffffu, mx, 1));
            mx = fmaxf(mx, __shfl_xor_sync(0xffffffffu, mx, 2));
            float e0 = __expf(lg0 - mx), e1 = __expf(lg1 - mx);
            float sm2 = e0 + e1;
            sm2 += __shfl_xor_sync(0xffffffffu, sm2, 1);
            sm2 += __shfl_xor_sync(0xffffffffu, sm2, 2);
            float inv = __fdividef(1.0f, sm2);
            a0f = e0 * inv; a1f = e1 * inv;
            if (w == 0)
                *(float2*)(out + OUT_ATTN + ((size_t)t * B_ + b) * 64 + md * 8 + n0)
                    = make_float2(a0f, a1f);
        }

        // ---- e: A_comm[w,h] = sum_m attn[m,w]*vcs[m,h]; state in regs
        {
            float sel = (w & 1) ? a1f : a0f;
            int srcq = w >> 1;
            float4 ac = make_float4(0.f, 0.f, 0.f, 0.f);
#pragma unroll
            for (int mm = 0; mm < 8; ++mm) {
                float av = __shfl_sync(0xffffffffu, sel, mm * 4 + srcq);
                float4 v = *(const float4*)(vcs + mm * 128 + h4);
                ac.x += av * v.x; ac.y += av * v.y;
                ac.z += av * v.z; ac.w += av * v.w;
            }
            float4 hnew = make_float4(hin.x + ac.x, hin.y + ac.y,
                                      hin.z + ac.z, hin.w + ac.w);
            size_t gbase = ((size_t)t * B_ + b) * MH_ + w * 128 + h4;
            *(float4*)(out + OUT_ACM + gbase) = ac;
            *(float4*)(out + OUT_HID + gbase) = hnew;
            s = hnew;
        }
        p4 = pn;
        par ^= 1;
    }
}

extern "C" void kernel_launch(void* const* d_in, const int* in_sizes, int n_in,
                              void* d_out, int out_size) {
    const float* x     = (const float*)d_in[0];
    const float* Wp    = (const float*)d_in[1];
    const float* bp    = (const float*)d_in[2];
    const float* U     = (const float*)d_in[3];
    const float* V     = (const float*)d_in[4];
    const float* cbias = (const float*)d_in[5];
    const float* W_in  = (const float*)d_in[6];
    const float* W_Q   = (const float*)d_in[7];
    const float* W_K   = (const float*)d_in[8];
    const float* W_V   = (const float*)d_in[9];
    const float* Wo    = (const float*)d_in[10];
    const float* bo    = (const float*)d_in[11];
    float* out = (float*)d_out;

    static bool attr_done = false;
    if (!attr_done) {
        cudaFuncSetAttribute(prep_wcomb,     cudaFuncAttributeMaxDynamicSharedMemorySize, 132608);
        cudaFuncSetAttribute(gemm_in_mma,    cudaFuncAttributeMaxDynamicSharedMemorySize, GEMM_SMEM);
        cudaFuncSetAttribute(gemm_out_mma,   cudaFuncAttributeMaxDynamicSharedMemorySize, GEMM_SMEM);
        cudaFuncSetAttribute(rim_seq_kernel, cudaFuncAttributeMaxDynamicSharedMemorySize, SEQ_SMEM);
        attr_done = true;
    }

    prep_wcomb<<<M_, 256, 132608>>>(W_in, Wp);
    prep_split<<<33, 256>>>(W_in, Wo, bp, cbias);
    gemm_in_mma<<<S_, 256, GEMM_SMEM>>>(x, out);
    rim_seq_kernel<<<B_, 256, SEQ_SMEM>>>(U, V, W_Q, W_K, W_V, out);
    gemm_out_mma<<<S_, 256, GEMM_SMEM>>>(bo, out);
}